// round 12
// baseline (speedup 1.0000x reference)
#include <cuda_runtime.h>

#define TPB 512
#define NBLOCKS 148
#define N_UNITS 1540   // 512 fwd-T + 1024 l + 4 center

// shared-memory layout (float offsets)
#define OFF_W11   0        // 128x8 row-major
#define OFF_B11   1024
#define OFF_W21   1152     // 128x8
#define OFF_B21   2176
#define OFF_W12T  2304     // 128x128 TRANSPOSED: [k][o]
#define OFF_B12   18688
#define OFF_W22T  18816    // 128x128 TRANSPOSED: [k][o]
#define OFF_B22   35200
#define OFF_WOUT  35328
#define OFF_Y     35456    // fwd: 128x128 [k][s] ; l: 128x64 [k][s]
#define OFF_YD    43648    // l only: 128x64 [k][s]
#define OFF_SCR   51840    // scheduler slot
#define SMEM_FLOATS 52096
#define SMEM_BYTES  (SMEM_FLOATS * 4)

using u64 = unsigned long long;

__device__ int g_unit_ctr;

__device__ __forceinline__ u64 fma2(u64 a, u64 b, u64 c) {
    u64 d; asm("fma.rn.f32x2 %0, %1, %2, %3;" : "=l"(d) : "l"(a), "l"(b), "l"(c)); return d;
}
__device__ __forceinline__ u64 mul2(u64 a, u64 b) {
    u64 d; asm("mul.rn.f32x2 %0, %1, %2;" : "=l"(d) : "l"(a), "l"(b)); return d;
}
__device__ __forceinline__ u64 dup2(float f) {
    u64 d; asm("mov.b64 %0, {%1, %1};" : "=l"(d) : "f"(f)); return d;
}
__device__ __forceinline__ void unpack2(u64 v, float& lo, float& hi) {
    asm("mov.b64 {%0, %1}, %2;" : "=f"(lo), "=f"(hi) : "l"(v));
}
__device__ __forceinline__ float red2(u64 v) {
    float lo, hi; unpack2(v, lo, hi); return lo + hi;
}
__device__ __forceinline__ float dot8(ulonglong2 w0, ulonglong2 w1,
                                      ulonglong2 xa, ulonglong2 xb) {
    u64 a = mul2(w0.x, xa.x);
    a = fma2(w0.y, xa.y, a);
    a = fma2(w1.x, xb.x, a);
    a = fma2(w1.y, xb.y, a);
    return red2(a);
}

__global__ void reset_kernel() { g_unit_ctr = NBLOCKS; }

__global__ __launch_bounds__(TPB, 1)
void net_kernel(const float* __restrict__ T, const float* __restrict__ L,
                const float* __restrict__ Ldot, const float* __restrict__ C,
                const float* __restrict__ w11, const float* __restrict__ b11,
                const float* __restrict__ w21, const float* __restrict__ b21,
                const float* __restrict__ w12, const float* __restrict__ b12,
                const float* __restrict__ w22, const float* __restrict__ b22,
                const float* __restrict__ wout, float* __restrict__ out)
{
    extern __shared__ float sm[];
    const int tid = threadIdx.x;

    // ---- weight staging (once per SM) ----
    for (int i = tid; i < 1024; i += TPB) sm[OFF_W11 + i] = w11[i];
    for (int i = tid; i < 1024; i += TPB) sm[OFF_W21 + i] = w21[i];
    if (tid < 128) {
        sm[OFF_B11 + tid] = b11[tid];
        sm[OFF_B21 + tid] = b21[tid];
        sm[OFF_B12 + tid] = b12[tid];
        sm[OFF_B22 + tid] = b22[tid];
        sm[OFF_WOUT + tid] = wout[tid];
    }
    // transpose W12, W22 into [k][o]
    {
        int o = tid & 127;
        int kq = tid >> 7;          // 0..3
        for (int kb = kq; kb < 32; kb += 4) {
            float4 v = *reinterpret_cast<const float4*>(&w12[o * 128 + kb * 4]);
            sm[OFF_W12T + (kb * 4 + 0) * 128 + o] = v.x;
            sm[OFF_W12T + (kb * 4 + 1) * 128 + o] = v.y;
            sm[OFF_W12T + (kb * 4 + 2) * 128 + o] = v.z;
            sm[OFF_W12T + (kb * 4 + 3) * 128 + o] = v.w;
            float4 u = *reinterpret_cast<const float4*>(&w22[o * 128 + kb * 4]);
            sm[OFF_W22T + (kb * 4 + 0) * 128 + o] = u.x;
            sm[OFF_W22T + (kb * 4 + 1) * 128 + o] = u.y;
            sm[OFF_W22T + (kb * 4 + 2) * 128 + o] = u.z;
            sm[OFF_W22T + (kb * 4 + 3) * 128 + o] = u.w;
        }
    }
    __syncthreads();

    // ---- persistent unit loop with dynamic scheduling ----
    // units: [0,512) fwd on T (128 samples), [512,1536) l (64 samples),
    //        [1536,1540) fwd on center (128 samples)
    int u = blockIdx.x;
    while (u < N_UNITS) {
        if (u < 512 || u >= 1536) {
            // =================== forward-only unit (T / center) ===================
            const float* base = (u < 512) ? T : C;
            const int obase   = (u < 512) ? 0 : 196608;
            const int sbase   = (u < 512) ? u * 128 : (u - 1536) * 128;

            // ---- phase 1: layer 1 -> y in shared [k][128], 4 threads/sample ----
            {
                const int s = tid & 127;
                const int q = tid >> 7;              // hidden quarter
                const float* xp = base + (size_t)(sbase + s) * 8;
                ulonglong2 xa = *reinterpret_cast<const ulonglong2*>(xp);
                ulonglong2 xb = *reinterpret_cast<const ulonglong2*>(xp + 4);
                #pragma unroll
                for (int j = 0; j < 32; ++j) {
                    int r = q * 32 + j;
                    const ulonglong2* ra = reinterpret_cast<const ulonglong2*>(&sm[OFF_W11 + r * 8]);
                    const ulonglong2* rc = reinterpret_cast<const ulonglong2*>(&sm[OFF_W21 + r * 8]);
                    float z1 = dot8(ra[0], ra[1], xa, xb) + sm[OFF_B11 + r];
                    float z2 = dot8(rc[0], rc[1], xa, xb) + sm[OFF_B21 + r];
                    sm[OFF_Y + r * 128 + s] = z1 * z2;
                }
            }
            __syncthreads();
            if (tid == 0) {
                int nu = atomicAdd(&g_unit_ctr, 1);
                *reinterpret_cast<int*>(&sm[OFF_SCR]) = nu;
            }

            // ---- phase 2: GEMM, thread tile = 8 samples x 4 outputs x 2 mats ----
            {
                const int ot = tid & 31;             // o-tile (4 outputs)
                const int st = tid >> 5;             // s-tile (8 samples)
                const int s0 = st * 8;
                const int ot4 = ot * 4;

                u64 A1[16], A2[16];
                #pragma unroll
                for (int i = 0; i < 16; ++i) { A1[i] = 0; A2[i] = 0; }

                #pragma unroll 2
                for (int k = 0; k < 128; ++k) {
                    ulonglong2 yA = *reinterpret_cast<const ulonglong2*>(&sm[OFF_Y + k * 128 + s0]);
                    ulonglong2 yB = *reinterpret_cast<const ulonglong2*>(&sm[OFF_Y + k * 128 + s0 + 4]);
                    float4 w1 = *reinterpret_cast<const float4*>(&sm[OFF_W12T + k * 128 + ot4]);
                    float4 w2 = *reinterpret_cast<const float4*>(&sm[OFF_W22T + k * 128 + ot4]);
                    float w1a[4] = {w1.x, w1.y, w1.z, w1.w};
                    float w2a[4] = {w2.x, w2.y, w2.z, w2.w};
                    #pragma unroll
                    for (int o = 0; o < 4; ++o) {
                        u64 d1 = dup2(w1a[o]);
                        u64 d2 = dup2(w2a[o]);
                        A1[o * 4 + 0] = fma2(d1, yA.x, A1[o * 4 + 0]);
                        A2[o * 4 + 0] = fma2(d2, yA.x, A2[o * 4 + 0]);
                        A1[o * 4 + 1] = fma2(d1, yA.y, A1[o * 4 + 1]);
                        A2[o * 4 + 1] = fma2(d2, yA.y, A2[o * 4 + 1]);
                        A1[o * 4 + 2] = fma2(d1, yB.x, A1[o * 4 + 2]);
                        A2[o * 4 + 2] = fma2(d2, yB.x, A2[o * 4 + 2]);
                        A1[o * 4 + 3] = fma2(d1, yB.y, A1[o * 4 + 3]);
                        A2[o * 4 + 3] = fma2(d2, yB.y, A2[o * 4 + 3]);
                    }
                }

                // epilogue: head dot, warp-reduce over the 32 o-tiles
                float part[8] = {0.f, 0.f, 0.f, 0.f, 0.f, 0.f, 0.f, 0.f};
                #pragma unroll
                for (int o = 0; o < 4; ++o) {
                    int og = ot4 + o;
                    float bo1 = sm[OFF_B12 + og], bo2 = sm[OFF_B22 + og], wo = sm[OFF_WOUT + og];
                    #pragma unroll
                    for (int sp = 0; sp < 4; ++sp) {
                        float u1l, u1h, u2l, u2h;
                        unpack2(A1[o * 4 + sp], u1l, u1h);
                        unpack2(A2[o * 4 + sp], u2l, u2h);
                        part[sp * 2]     = fmaf(wo, (u1l + bo1) * (u2l + bo2), part[sp * 2]);
                        part[sp * 2 + 1] = fmaf(wo, (u1h + bo1) * (u2h + bo2), part[sp * 2 + 1]);
                    }
                }
                #pragma unroll
                for (int i = 0; i < 8; ++i) {
                    #pragma unroll
                    for (int m = 16; m > 0; m >>= 1)
                        part[i] += __shfl_xor_sync(0xffffffffu, part[i], m);
                }
                if ((tid & 31) == 0) {
                    #pragma unroll
                    for (int i = 0; i < 8; ++i)
                        out[obase + sbase + s0 + i] = part[i];
                }
            }
        } else {
            // =================== l unit: forward + JVP (64 samples) ===================
            const int sbase = (u - 512) * 64;

            // ---- phase 1: layer 1 -> y, yd in shared [k][64], 8 threads/sample ----
            {
                const int s = tid & 63;
                const int p = tid >> 6;              // 0..7, 16 rows each
                const float* xp = L    + (size_t)(sbase + s) * 8;
                const float* dp = Ldot + (size_t)(sbase + s) * 8;
                ulonglong2 xa = *reinterpret_cast<const ulonglong2*>(xp);
                ulonglong2 xb = *reinterpret_cast<const ulonglong2*>(xp + 4);
                ulonglong2 da = *reinterpret_cast<const ulonglong2*>(dp);
                ulonglong2 db = *reinterpret_cast<const ulonglong2*>(dp + 4);
                #pragma unroll
                for (int j = 0; j < 16; ++j) {
                    int r = p * 16 + j;
                    const ulonglong2* ra = reinterpret_cast<const ulonglong2*>(&sm[OFF_W11 + r * 8]);
                    const ulonglong2* rc = reinterpret_cast<const ulonglong2*>(&sm[OFF_W21 + r * 8]);
                    ulonglong2 q0 = ra[0], q1 = ra[1];
                    ulonglong2 m0 = rc[0], m1 = rc[1];
                    float z1  = dot8(q0, q1, xa, xb) + sm[OFF_B11 + r];
                    float z2  = dot8(m0, m1, xa, xb) + sm[OFF_B21 + r];
                    float z1d = dot8(q0, q1, da, db);
                    float z2d = dot8(m0, m1, da, db);
                    sm[OFF_Y  + r * 64 + s] = z1 * z2;
                    sm[OFF_YD + r * 64 + s] = fmaf(z1d, z2, z1 * z2d);
                }
            }
            __syncthreads();
            if (tid == 0) {
                int nu = atomicAdd(&g_unit_ctr, 1);
                *reinterpret_cast<int*>(&sm[OFF_SCR]) = nu;
            }

            // ---- phase 2: tile = 4 samples x 4 outputs, 1.0 B/MAC ----
            {
                const int ot = tid & 31;             // o-tile (4 outputs), spans one warp
                const int st = tid >> 5;             // s-tile (4 samples), one per warp
                const int s0 = st * 4;
                const int ot4 = ot * 4;

                u64 C1[8], C2[8], E1[8], E2[8];      // [o][sample-pair]
                #pragma unroll
                for (int i = 0; i < 8; ++i) { C1[i] = 0; C2[i] = 0; E1[i] = 0; E2[i] = 0; }

                #pragma unroll 2
                for (int k = 0; k < 128; ++k) {
                    ulonglong2 yP = *reinterpret_cast<const ulonglong2*>(&sm[OFF_Y  + k * 64 + s0]);
                    ulonglong2 gP = *reinterpret_cast<const ulonglong2*>(&sm[OFF_YD + k * 64 + s0]);
                    float4 w1 = *reinterpret_cast<const float4*>(&sm[OFF_W12T + k * 128 + ot4]);
                    float4 w2 = *reinterpret_cast<const float4*>(&sm[OFF_W22T + k * 128 + ot4]);
                    float w1a[4] = {w1.x, w1.y, w1.z, w1.w};
                    float w2a[4] = {w2.x, w2.y, w2.z, w2.w};
                    #pragma unroll
                    for (int o = 0; o < 4; ++o) {
                        u64 d1 = dup2(w1a[o]);
                        u64 d2 = dup2(w2a[o]);
                        C1[o * 2 + 0] = fma2(d1, yP.x, C1[o * 2 + 0]);
                        C2[o * 2 + 0] = fma2(d2, yP.x, C2[o * 2 + 0]);
                        E1[o * 2 + 0] = fma2(d1, gP.x, E1[o * 2 + 0]);
                        E2[o * 2 + 0] = fma2(d2, gP.x, E2[o * 2 + 0]);
                        C1[o * 2 + 1] = fma2(d1, yP.y, C1[o * 2 + 1]);
                        C2[o * 2 + 1] = fma2(d2, yP.y, C2[o * 2 + 1]);
                        E1[o * 2 + 1] = fma2(d1, gP.y, E1[o * 2 + 1]);
                        E2[o * 2 + 1] = fma2(d2, gP.y, E2[o * 2 + 1]);
                    }
                }

                // epilogue: per-lane head partials, then warp-reduce over 32 o-tiles
                float vp[4] = {0.f, 0.f, 0.f, 0.f};
                float gp[4] = {0.f, 0.f, 0.f, 0.f};
                #pragma unroll
                for (int o = 0; o < 4; ++o) {
                    int og = ot4 + o;
                    float bo1 = sm[OFF_B12 + og], bo2 = sm[OFF_B22 + og], wo = sm[OFF_WOUT + og];
                    #pragma unroll
                    for (int sp = 0; sp < 2; ++sp) {
                        float u1l, u1h, u2l, u2h, d1l, d1h, d2l, d2h;
                        unpack2(C1[o * 2 + sp], u1l, u1h);
                        unpack2(C2[o * 2 + sp], u2l, u2h);
                        unpack2(E1[o * 2 + sp], d1l, d1h);
                        unpack2(E2[o * 2 + sp], d2l, d2h);
                        float a1l = u1l + bo1, a2l = u2l + bo2;
                        float a1h = u1h + bo1, a2h = u2h + bo2;
                        vp[sp * 2]     = fmaf(wo, a1l * a2l, vp[sp * 2]);
                        gp[sp * 2]     = fmaf(wo, fmaf(d1l, a2l, a1l * d2l), gp[sp * 2]);
                        vp[sp * 2 + 1] = fmaf(wo, a1h * a2h, vp[sp * 2 + 1]);
                        gp[sp * 2 + 1] = fmaf(wo, fmaf(d1h, a2h, a1h * d2h), gp[sp * 2 + 1]);
                    }
                }
                #pragma unroll
                for (int i = 0; i < 4; ++i) {
                    #pragma unroll
                    for (int m = 16; m > 0; m >>= 1) {
                        vp[i] += __shfl_xor_sync(0xffffffffu, vp[i], m);
                        gp[i] += __shfl_xor_sync(0xffffffffu, gp[i], m);
                    }
                }
                if ((tid & 31) == 0) {
                    #pragma unroll
                    for (int i = 0; i < 4; ++i) {
                        out[65536  + sbase + s0 + i] = vp[i];
                        out[131072 + sbase + s0 + i] = gp[i];
                    }
                }
            }
        }
        __syncthreads();
        u = *reinterpret_cast<const int*>(&sm[OFF_SCR]);
    }
}

extern "C" void kernel_launch(void* const* d_in, const int* in_sizes, int n_in,
                              void* d_out, int out_size)
{
    const float* T    = (const float*)d_in[0];
    const float* L    = (const float*)d_in[1];
    const float* Ldot = (const float*)d_in[2];
    const float* C    = (const float*)d_in[3];
    const float* w11  = (const float*)d_in[4];
    const float* b11  = (const float*)d_in[5];
    const float* w21  = (const float*)d_in[6];
    const float* b21  = (const float*)d_in[7];
    const float* w12  = (const float*)d_in[8];
    const float* b12  = (const float*)d_in[9];
    const float* w22  = (const float*)d_in[10];
    const float* b22  = (const float*)d_in[11];
    const float* wout = (const float*)d_in[12];
    float* out = (float*)d_out;

    cudaFuncSetAttribute(net_kernel, cudaFuncAttributeMaxDynamicSharedMemorySize, SMEM_BYTES);

    reset_kernel<<<1, 1>>>();
    net_kernel<<<NBLOCKS, TPB, SMEM_BYTES>>>(T, L, Ldot, C,
                                             w11, b11, w21, b21,
                                             w12, b12, w22, b22,
                                             wout, out);
}